// round 6
// baseline (speedup 1.0000x reference)
#include <cuda_runtime.h>
#include <math.h>

#define NMAX 32
#define BMAX 8
#define LEVELS 6

// SIZES computed in double then rounded to f32, matching numpy/jax promotion.
__device__ const float d_SIZES[LEVELS] = {
    (float)(2.23147392 * 22050.0 / 256.0),
    (float)(2.62519274 * 22050.0 / 256.0),
    (float)(3.74199546 * 22050.0 / 256.0),
    (float)(5.78800454 * 22050.0 / 256.0),
    (float)(8.02371882 * 22050.0 / 256.0),
    INFINITY
};

__device__ float g_ss[BMAX][NMAX];        // sorted starts
__device__ float g_ee[BMAX][NMAX];        // sorted ends
__device__ int2  g_iv[BMAX][NMAX][LEVELS];// conservative anchor-index intervals
__device__ float g_loss[BMAX];
__device__ float g_cnt[BMAX];

// ---------------------------------------------------------------------------
// K0: stable sort annotations by length (rank sort), zero accumulators,
//     compute conservative candidate intervals per (sample, ann, level).
// ---------------------------------------------------------------------------
__global__ void k_setup(const float* __restrict__ ann, int B, int L0) {
    __shared__ float sh_s[BMAX][NMAX], sh_e[BMAX][NMAX], sh_len[BMAX][NMAX];
    __shared__ float st_s[BMAX][NMAX], st_e[BMAX][NMAX]; // sorted

    int t = threadIdx.x;
    int total = B * NMAX;

    if (t < total) {
        int b = t / NMAX, j = t % NMAX;
        float s = ann[t * 3 + 0];
        float e = ann[t * 3 + 1];
        sh_s[b][j] = s;
        sh_e[b][j] = e;
        sh_len[b][j] = e - s;
    }
    if (t < B) { g_loss[t] = 0.0f; g_cnt[t] = 0.0f; }
    __syncthreads();

    if (t < total) {
        int b = t / NMAX, j = t % NMAX;
        float lj = sh_len[b][j];
        int rank = 0;
        #pragma unroll
        for (int k = 0; k < NMAX; k++) {
            float lk = sh_len[b][k];
            rank += (lk < lj) || (lk == lj && k < j);
        }
        float s = sh_s[b][j], e = sh_e[b][j];
        st_s[b][rank] = s;
        st_e[b][rank] = e;
        g_ss[b][rank] = s;
        g_ee[b][rank] = e;
    }
    __syncthreads();

    for (int u = t; u < B * NMAX * LEVELS; u += blockDim.x) {
        int b = u / (NMAX * LEVELS);
        int rj = u % (NMAX * LEVELS);
        int j = rj / LEVELS;
        int i = rj % LEVELS;

        float s = st_s[b][j], e = st_e[b][j];
        float len = e - s;
        float lower = (i > 0) ? d_SIZES[i - 1] : 0.0f;
        float upper = d_SIZES[i];

        int2 iv;
        iv.x = 1; iv.y = 0; // empty
        // m <= len exactly (monotone rounding), so len < lower => no cand ever.
        if (len >= lower) {
            float lo_pt = fmaxf(s, e - upper);   // e - inf = -inf -> s
            float hi_pt = fminf(e, s + upper);   // s + inf = inf  -> e
            float inv = 1.0f / (float)(1 << i);
            int klo = (int)floorf(lo_pt * inv - 0.5f) - 2;
            int khi = (int)ceilf (hi_pt * inv - 0.5f) + 2;
            int Li = L0 >> i;
            klo = klo < 0 ? 0 : klo;
            khi = khi > Li - 1 ? Li - 1 : khi;
            if (klo <= khi) { iv.x = klo; iv.y = khi; }
        }
        g_iv[b][j][i] = iv;
    }
}

// ---------------------------------------------------------------------------
// K1: one block per (sample, annotation j, level i). For each anchor in the
//     conservative interval: exact cand test (bit-identical to reference);
//     winner iff no j' < j is cand; then GIoU contribution.
// ---------------------------------------------------------------------------
__global__ void k_main(const float* __restrict__ reg, int A, int L0) {
    int bid = blockIdx.x;
    int b = bid / (NMAX * LEVELS);
    int rem = bid % (NMAX * LEVELS);
    int j = rem / LEVELS;
    int i = rem % LEVELS;

    int2 iv = g_iv[b][j][i];

    float lsum = 0.0f, lcnt = 0.0f;

    if (iv.x <= iv.y) {
        __shared__ float sh_s[NMAX], sh_e[NMAX];
        int t = threadIdx.x;
        if (t < NMAX) { sh_s[t] = g_ss[b][t]; sh_e[t] = g_ee[b][t]; }
        __syncthreads();

        float sj = sh_s[j], ej = sh_e[j];
        float scale = (float)(1 << i);
        float inv = 1.0f / scale;
        float lower = (i > 0) ? d_SIZES[i - 1] : 0.0f;
        float upper = d_SIZES[i];

        int off = 0;
        #pragma unroll
        for (int q = 0; q < LEVELS; q++) off += (q < i) ? (L0 >> q) : 0;

        for (int a = iv.x + t; a <= iv.y; a += blockDim.x) {
            float pt = ((float)a + 0.5f) * scale;
            float l = pt - sj;
            float r = ej - pt;
            float m = fmaxf(l, r);
            bool cand = (l >= 0.0f) & (r >= 0.0f) & (m >= lower) & (m < upper);
            if (!cand) continue;

            // first-wins: reject if any smaller-length annotation is also cand
            bool first = true;
            for (int jp = 0; jp < j; jp++) {
                float l2 = pt - sh_s[jp];
                float r2 = sh_e[jp] - pt;
                float m2 = fmaxf(l2, r2);
                if ((l2 >= 0.0f) & (r2 >= 0.0f) & (m2 >= lower) & (m2 < upper)) {
                    first = false;
                    break;
                }
            }
            if (!first) continue;

            float nl = l * inv;
            float nr = r * inv;
            float a0 = pt - nl;
            float a1 = pt + nr;

            const float2 rb = ((const float2*)reg)[(size_t)b * A + off + a];
            float b0 = rb.x, b1 = rb.y;

            float inter = fminf(a1, b1) - fmaxf(a0, b0);
            inter = fmaxf(inter, 0.0f);
            float uni = (a1 - a0) + (b1 - b0) - inter;
            float iou = inter / (uni + 1e-7f);
            float enc = fmaxf(a1, b1) - fminf(a0, b0);
            float giou = iou - (enc - uni) / (enc + 1e-7f);
            giou = fminf(fmaxf(giou, -1.0f), 1.0f);

            lsum += 1.0f - giou;
            lcnt += 1.0f;
        }
    }

    // warp reduction, then sparse atomics (only warps with hits)
    #pragma unroll
    for (int o = 16; o > 0; o >>= 1) {
        lsum += __shfl_down_sync(0xFFFFFFFFu, lsum, o);
        lcnt += __shfl_down_sync(0xFFFFFFFFu, lcnt, o);
    }
    if ((threadIdx.x & 31) == 0 && lcnt > 0.0f) {
        atomicAdd(&g_loss[b], lsum);
        atomicAdd(&g_cnt[b], lcnt);
    }
}

// ---------------------------------------------------------------------------
// K2: finalize
// ---------------------------------------------------------------------------
__global__ void k_final(float* __restrict__ out, int B) {
    int b = threadIdx.x;
    if (b < B) out[b] = g_loss[b] / fmaxf(g_cnt[b], 1.0f);
}

// ---------------------------------------------------------------------------
// Launch. Inputs identified by element count (robust to metadata ordering):
//   regressions = max size; class_id = 1; anchors = power-of-two sizes (>1);
//   annotations = the remaining input. B = ann_size / 96.
// ---------------------------------------------------------------------------
extern "C" void kernel_launch(void* const* d_in, const int* in_sizes, int n_in,
                              void* d_out, int out_size) {
    int reg_i = -1;
    long reg_sz = -1;
    for (int i = 0; i < n_in; i++) {
        if ((long)in_sizes[i] > reg_sz) { reg_sz = in_sizes[i]; reg_i = i; }
    }
    int ann_i = -1;
    int L0 = 0;
    for (int i = 0; i < n_in; i++) {
        if (i == reg_i) continue;
        int s = in_sizes[i];
        if (s <= 1) continue;                 // class_id
        bool pow2 = (s & (s - 1)) == 0;
        if (pow2) { if (s > L0) L0 = s; }     // anchors; L0 = largest level
        else       { ann_i = i; }             // annotations (B*32*3, not pow2)
    }

    int B = in_sizes[ann_i] / (NMAX * 3);
    if (B > BMAX) B = BMAX;
    int A = (int)(reg_sz / (2 * B));

    const float* reg = (const float*)d_in[reg_i];
    const float* ann = (const float*)d_in[ann_i];
    float* out = (float*)d_out;

    k_setup<<<1, 256>>>(ann, B, L0);
    k_main<<<B * NMAX * LEVELS, 128>>>(reg, A, L0);
    k_final<<<1, 32>>>(out, B);
}

// round 8
// speedup vs baseline: 1.0717x; 1.0717x over previous
#include <cuda_runtime.h>
#include <math.h>

#define NMAX 32
#define BMAX 8
#define LEVELS 6

// SIZES computed in double then rounded to f32, matching numpy/jax promotion.
__device__ const float d_SIZES[LEVELS] = {
    (float)(2.23147392 * 22050.0 / 256.0),
    (float)(2.62519274 * 22050.0 / 256.0),
    (float)(3.74199546 * 22050.0 / 256.0),
    (float)(5.78800454 * 22050.0 / 256.0),
    (float)(8.02371882 * 22050.0 / 256.0),
    INFINITY
};

// Persistent accumulators. Zero-initialized at module load; the last block of
// every launch resets them to zero again, so each launch/replay starts clean.
__device__ float    g_loss[BMAX];
__device__ float    g_cnt[BMAX];
__device__ unsigned g_counter;

// ---------------------------------------------------------------------------
// Fused kernel: one block per (sample b, sorted-annotation j, level i).
//   1. Redundantly rank-sort the 32 annotations of sample b (stable, by length)
//      in shared memory (32x32 compares — cheaper than a separate launch).
//   2. Compute the conservative candidate anchor-index interval for (j, i).
//   3. For each anchor in the interval: exact cand test (bit-identical to the
//      reference), first-j-wins check against smaller annotations, GIoU.
//   4. Warp-reduce, atomically accumulate, and let the LAST block finalize
//      out[b] = loss/max(cnt,1) and reset the accumulators for the next replay.
// ---------------------------------------------------------------------------
__global__ void k_fused(const float* __restrict__ ann,
                        const float* __restrict__ reg,
                        float* __restrict__ out,
                        int B, int L0, int A) {
    const int bid = blockIdx.x;
    const int b   = bid / (NMAX * LEVELS);
    const int rem = bid % (NMAX * LEVELS);
    const int j   = rem / LEVELS;
    const int i   = rem % LEVELS;

    __shared__ float sh_s[NMAX], sh_e[NMAX];           // sorted by length
    __shared__ float raw_s[NMAX], raw_e[NMAX], raw_len[NMAX];
    __shared__ bool  is_last;

    const int t = threadIdx.x;

    // --- load + stable rank sort (threads 0..31) ---
    if (t < NMAX) {
        float s = ann[(b * NMAX + t) * 3 + 0];
        float e = ann[(b * NMAX + t) * 3 + 1];
        raw_s[t] = s; raw_e[t] = e; raw_len[t] = e - s;
    }
    __syncthreads();
    if (t < NMAX) {
        float lj = raw_len[t];
        int rank = 0;
        #pragma unroll
        for (int k = 0; k < NMAX; k++) {
            float lk = raw_len[k];
            rank += (lk < lj) || (lk == lj && k < t);
        }
        sh_s[rank] = raw_s[t];
        sh_e[rank] = raw_e[t];
    }
    __syncthreads();

    // --- per-block constants ---
    const float sj    = sh_s[j];
    const float ej    = sh_e[j];
    const float scale = (float)(1 << i);
    const float inv   = 1.0f / scale;
    const float lower = (i > 0) ? d_SIZES[i - 1] : 0.0f;
    const float upper = d_SIZES[i];

    // --- conservative candidate interval for (j, i) ---
    int klo = 1, khi = 0;                 // empty
    {
        float len = ej - sj;
        // m <= len (monotone fp rounding), so len < lower => no cand ever.
        if (len >= lower) {
            float lo_pt = fmaxf(sj, ej - upper);   // e - inf -> s
            float hi_pt = fminf(ej, sj + upper);   // s + inf -> e
            int lo = (int)floorf(lo_pt * inv - 0.5f) - 2;
            int hi = (int)ceilf (hi_pt * inv - 0.5f) + 2;
            int Li = L0 >> i;
            lo = lo < 0 ? 0 : lo;
            hi = hi > Li - 1 ? Li - 1 : hi;
            if (lo <= hi) { klo = lo; khi = hi; }
        }
    }

    // anchor-row offset of level i within the concatenated pyramid
    int off = 0;
    #pragma unroll
    for (int q = 0; q < LEVELS; q++) off += (q < i) ? (L0 >> q) : 0;

    float lsum = 0.0f, lcnt = 0.0f;

    for (int a = klo + t; a <= khi; a += blockDim.x) {
        float pt = ((float)a + 0.5f) * scale;
        float l = pt - sj;
        float r = ej - pt;
        float m = fmaxf(l, r);
        bool cand = (l >= 0.0f) & (r >= 0.0f) & (m >= lower) & (m < upper);
        if (!cand) continue;

        // first-wins: reject if any smaller-length annotation is also cand
        bool first = true;
        for (int jp = 0; jp < j; jp++) {
            float l2 = pt - sh_s[jp];
            float r2 = sh_e[jp] - pt;
            float m2 = fmaxf(l2, r2);
            if ((l2 >= 0.0f) & (r2 >= 0.0f) & (m2 >= lower) & (m2 < upper)) {
                first = false;
                break;
            }
        }
        if (!first) continue;

        float nl = l * inv;
        float nr = r * inv;
        float a0 = pt - nl;
        float a1 = pt + nr;

        const float2 rb = ((const float2*)reg)[(size_t)b * A + off + a];
        float b0 = rb.x, b1 = rb.y;

        float inter = fminf(a1, b1) - fmaxf(a0, b0);
        inter = fmaxf(inter, 0.0f);
        float uni = (a1 - a0) + (b1 - b0) - inter;
        float iou = inter / (uni + 1e-7f);
        float enc = fmaxf(a1, b1) - fminf(a0, b0);
        float giou = iou - (enc - uni) / (enc + 1e-7f);
        giou = fminf(fmaxf(giou, -1.0f), 1.0f);

        lsum += 1.0f - giou;
        lcnt += 1.0f;
    }

    // --- warp reduction, sparse atomics ---
    #pragma unroll
    for (int o = 16; o > 0; o >>= 1) {
        lsum += __shfl_down_sync(0xFFFFFFFFu, lsum, o);
        lcnt += __shfl_down_sync(0xFFFFFFFFu, lcnt, o);
    }
    if ((t & 31) == 0 && lcnt > 0.0f) {
        atomicAdd(&g_loss[b], lsum);
        atomicAdd(&g_cnt[b], lcnt);
    }

    // --- last-block finalize (threadfence-reduction pattern) ---
    __threadfence();
    if (t == 0) {
        unsigned v = atomicAdd(&g_counter, 1u);
        is_last = (v == gridDim.x - 1);
    }
    __syncthreads();
    if (is_last) {
        if (t < B) {
            // read through L2 (atomic) to avoid any L1 ordering question
            float ls = atomicAdd(&g_loss[t], 0.0f);
            float cn = atomicAdd(&g_cnt[t], 0.0f);
            out[t] = ls / fmaxf(cn, 1.0f);
            g_loss[t] = 0.0f;
            g_cnt[t]  = 0.0f;
        }
        if (t == 0) g_counter = 0;
    }
}

// ---------------------------------------------------------------------------
// Launch. Inputs identified by element count (robust to metadata ordering):
//   regressions = max size; class_id = 1; anchors = power-of-two sizes (>1);
//   annotations = the remaining input. B = ann_size / 96.
// ---------------------------------------------------------------------------
extern "C" void kernel_launch(void* const* d_in, const int* in_sizes, int n_in,
                              void* d_out, int out_size) {
    int reg_i = -1;
    long reg_sz = -1;
    for (int i = 0; i < n_in; i++) {
        if ((long)in_sizes[i] > reg_sz) { reg_sz = in_sizes[i]; reg_i = i; }
    }
    int ann_i = -1;
    int L0 = 0;
    for (int i = 0; i < n_in; i++) {
        if (i == reg_i) continue;
        int s = in_sizes[i];
        if (s <= 1) continue;                 // class_id
        bool pow2 = (s & (s - 1)) == 0;
        if (pow2) { if (s > L0) L0 = s; }     // anchors; L0 = largest level
        else       { ann_i = i; }             // annotations (B*32*3, not pow2)
    }

    int B = in_sizes[ann_i] / (NMAX * 3);
    if (B > BMAX) B = BMAX;
    int A = (int)(reg_sz / (2 * B));

    const float* reg = (const float*)d_in[reg_i];
    const float* ann = (const float*)d_in[ann_i];
    float* out = (float*)d_out;

    k_fused<<<B * NMAX * LEVELS, 128>>>(ann, reg, out, B, L0, A);
}

// round 9
// speedup vs baseline: 1.2694x; 1.1845x over previous
#include <cuda_runtime.h>
#include <math.h>

#define NMAX 32
#define BMAX 8
#define LEVELS 6

// SIZES computed in double then rounded to f32, matching numpy/jax promotion.
__device__ const float d_SIZES[LEVELS] = {
    (float)(2.23147392 * 22050.0 / 256.0),
    (float)(2.62519274 * 22050.0 / 256.0),
    (float)(3.74199546 * 22050.0 / 256.0),
    (float)(5.78800454 * 22050.0 / 256.0),
    (float)(8.02371882 * 22050.0 / 256.0),
    INFINITY
};

// Persistent accumulators. Zero-initialized at module load; the last block of
// every launch resets them, so each launch/replay starts clean.
__device__ float    g_loss[BMAX];
__device__ float    g_cnt[BMAX];
__device__ unsigned g_counter;

__device__ __forceinline__ float ld_l2(const float* p) {
    float v;
    asm volatile("ld.global.cg.f32 %0, [%1];" : "=f"(v) : "l"(p));
    return v;
}

// ---------------------------------------------------------------------------
// Fused kernel, sort-free formulation.
// One block per (sample b, ORIGINAL annotation index j, level i).
// An anchor's winner in the reference = the cand annotation minimizing
// (length, original index) lexicographically (stable argsort by length, then
// argmax-of-bool = first in sorted order). So block (b,j,i) contributes anchor
// a iff: cand(j,a,i) AND no k != j with (len_k,k) <lex (len_j,j) has cand(k,a,i).
// All cand tests are bit-identical to the reference's arithmetic.
// ---------------------------------------------------------------------------
__global__ void k_fused(const float* __restrict__ ann,
                        const float* __restrict__ reg,
                        float* __restrict__ out,
                        int B, int L0, int A) {
    const int bid = blockIdx.x;
    const int b   = bid / (NMAX * LEVELS);
    const int rem = bid % (NMAX * LEVELS);
    const int j   = rem / LEVELS;
    const int i   = rem % LEVELS;

    __shared__ float sh_s[NMAX], sh_e[NMAX], sh_len[NMAX];

    const int t = threadIdx.x;

    // --- load annotations (unsorted) straight into smem, one sync ---
    if (t < NMAX) {
        float s = ann[(b * NMAX + t) * 3 + 0];
        float e = ann[(b * NMAX + t) * 3 + 1];
        sh_s[t] = s; sh_e[t] = e; sh_len[t] = e - s;
    }
    __syncthreads();

    // --- per-block constants ---
    const float sj    = sh_s[j];
    const float ej    = sh_e[j];
    const float lenj  = sh_len[j];
    const float scale = (float)(1 << i);
    const float inv   = 1.0f / scale;
    const float lower = (i > 0) ? d_SIZES[i - 1] : 0.0f;
    const float upper = d_SIZES[i];

    // --- conservative candidate interval for (j, i) ---
    int klo = 1, khi = 0;                 // empty
    {
        // m <= len (monotone fp rounding), so len < lower => no cand ever.
        if (lenj >= lower) {
            float lo_pt = fmaxf(sj, ej - upper);   // e - inf -> s
            float hi_pt = fminf(ej, sj + upper);   // s + inf -> e
            int lo = (int)floorf(lo_pt * inv - 0.5f) - 2;
            int hi = (int)ceilf (hi_pt * inv - 0.5f) + 2;
            int Li = L0 >> i;
            lo = lo < 0 ? 0 : lo;
            hi = hi > Li - 1 ? Li - 1 : hi;
            if (lo <= hi) { klo = lo; khi = hi; }
        }
    }

    // anchor-row offset of level i within the concatenated pyramid
    int off = 0;
    #pragma unroll
    for (int q = 0; q < LEVELS; q++) off += (q < i) ? (L0 >> q) : 0;

    float lsum = 0.0f, lcnt = 0.0f;

    for (int a = klo + t; a <= khi; a += blockDim.x) {
        float pt = ((float)a + 0.5f) * scale;
        float l = pt - sj;
        float r = ej - pt;
        float m = fmaxf(l, r);
        bool cand = (l >= 0.0f) & (r >= 0.0f) & (m >= lower) & (m < upper);
        if (!cand) continue;

        // Issue the regression load NOW so its DRAM latency overlaps the
        // winner scan below.
        const float2 rb = __ldcg(&((const float2*)reg)[(size_t)b * A + off + a]);

        // winner iff no annotation with lexicographically smaller (len, idx)
        // is also cand at this anchor+level.
        bool first = true;
        #pragma unroll 4
        for (int k = 0; k < NMAX; k++) {
            float lk = sh_len[k];
            bool smaller = (lk < lenj) || (lk == lenj && k < j);
            if (!smaller) continue;
            float l2 = pt - sh_s[k];
            float r2 = sh_e[k] - pt;
            float m2 = fmaxf(l2, r2);
            if ((l2 >= 0.0f) & (r2 >= 0.0f) & (m2 >= lower) & (m2 < upper)) {
                first = false;
                break;
            }
        }
        if (!first) continue;

        float nl = l * inv;
        float nr = r * inv;
        float a0 = pt - nl;
        float a1 = pt + nr;
        float b0 = rb.x, b1 = rb.y;

        float inter = fminf(a1, b1) - fmaxf(a0, b0);
        inter = fmaxf(inter, 0.0f);
        float uni = (a1 - a0) + (b1 - b0) - inter;
        float iou = __fdividef(inter, uni + 1e-7f);
        float enc = fmaxf(a1, b1) - fminf(a0, b0);
        float giou = iou - __fdividef(enc - uni, enc + 1e-7f);
        giou = fminf(fmaxf(giou, -1.0f), 1.0f);

        lsum += 1.0f - giou;
        lcnt += 1.0f;
    }

    // --- warp reduction, sparse atomics (REDG: no return value used) ---
    #pragma unroll
    for (int o = 16; o > 0; o >>= 1) {
        lsum += __shfl_down_sync(0xFFFFFFFFu, lsum, o);
        lcnt += __shfl_down_sync(0xFFFFFFFFu, lcnt, o);
    }
    if ((t & 31) == 0 && lcnt > 0.0f) {
        atomicAdd(&g_loss[b], lsum);
        atomicAdd(&g_cnt[b], lcnt);
    }

    // --- last-block finalize; only warp 0 participates past the sync ---
    __threadfence();
    __syncthreads();            // all block atomics issued before counter bump
    if (t < 32) {
        unsigned v = 0;
        if (t == 0) v = atomicAdd(&g_counter, 1u);
        v = __shfl_sync(0xFFFFFFFFu, v, 0);
        if (v == gridDim.x - 1) {
            if (t < B) {
                // prior updates are L2 atomics + fence: read via L2 (ld.cg)
                float ls = ld_l2(&g_loss[t]);
                float cn = ld_l2(&g_cnt[t]);
                out[t] = __fdividef(ls, fmaxf(cn, 1.0f));
                g_loss[t] = 0.0f;
                g_cnt[t]  = 0.0f;
            }
            if (t == 0) g_counter = 0;
        }
    }
}

// ---------------------------------------------------------------------------
// Launch. Inputs identified by element count (robust to metadata ordering):
//   regressions = max size; class_id = 1; anchors = power-of-two sizes (>1);
//   annotations = the remaining input. B = ann_size / 96.
// ---------------------------------------------------------------------------
extern "C" void kernel_launch(void* const* d_in, const int* in_sizes, int n_in,
                              void* d_out, int out_size) {
    int reg_i = -1;
    long reg_sz = -1;
    for (int i = 0; i < n_in; i++) {
        if ((long)in_sizes[i] > reg_sz) { reg_sz = in_sizes[i]; reg_i = i; }
    }
    int ann_i = -1;
    int L0 = 0;
    for (int i = 0; i < n_in; i++) {
        if (i == reg_i) continue;
        int s = in_sizes[i];
        if (s <= 1) continue;                 // class_id
        bool pow2 = (s & (s - 1)) == 0;
        if (pow2) { if (s > L0) L0 = s; }     // anchors; L0 = largest level
        else       { ann_i = i; }             // annotations (B*32*3, not pow2)
    }

    int B = in_sizes[ann_i] / (NMAX * 3);
    if (B > BMAX) B = BMAX;
    int A = (int)(reg_sz / (2 * B));

    const float* reg = (const float*)d_in[reg_i];
    const float* ann = (const float*)d_in[ann_i];
    float* out = (float*)d_out;

    k_fused<<<B * NMAX * LEVELS, 128>>>(ann, reg, out, B, L0, A);
}